// round 2
// baseline (speedup 1.0000x reference)
#include <cuda_runtime.h>
#include <stdint.h>

#define BB 4
#define SS 2048
#define DD 1024
#define DVV 64
#define SCALE 0.125f      // 1/sqrt(64)
#define LNEPS 1e-6f

#define OUT_ELEMS (BB*SS*DD)       // 8388608  (output part of tuple)
// attn part of tuple lives at d_out + OUT_ELEMS, size B*S*S = 16777216

// scratch (no allocations allowed)
__device__ float g_qs[BB*SS*DD];   // layernormed+scaled q
__device__ float g_w[DD];          // fc_w @ V

// ---------------------------------------------------------------------------
// w[d] = sum_dv fc_w[d,dv] * V[dv]
__global__ void k_w(const float* __restrict__ fc_w, const float* __restrict__ V) {
    int d = blockIdx.x * blockDim.x + threadIdx.x;
    if (d < DD) {
        float s = 0.f;
        #pragma unroll
        for (int i = 0; i < DVV; i++) s += fc_w[d * DVV + i] * V[i];
        g_w[d] = s;
    }
}

// ---------------------------------------------------------------------------
// LayerNorm + scale. One block (256 thr) per row of 1024.
__global__ void k_ln(const float* __restrict__ q,
                     const float* __restrict__ lng,
                     const float* __restrict__ lnb) {
    int row = blockIdx.x;
    const float4* x4 = (const float4*)(q + (size_t)row * DD);
    float4 v = x4[threadIdx.x];
    float sum = v.x + v.y + v.z + v.w;
    float sq  = v.x * v.x + v.y * v.y + v.z * v.z + v.w * v.w;

    __shared__ float ssum[8], ssq[8];
    __shared__ float s_mu, s_rstd;
    #pragma unroll
    for (int off = 16; off > 0; off >>= 1) {
        sum += __shfl_down_sync(0xffffffffu, sum, off);
        sq  += __shfl_down_sync(0xffffffffu, sq,  off);
    }
    int wid = threadIdx.x >> 5, lid = threadIdx.x & 31;
    if (lid == 0) { ssum[wid] = sum; ssq[wid] = sq; }
    __syncthreads();
    if (threadIdx.x == 0) {
        float ts = 0.f, tq = 0.f;
        #pragma unroll
        for (int i = 0; i < 8; i++) { ts += ssum[i]; tq += ssq[i]; }
        float mu  = ts * (1.0f / DD);
        float var = tq * (1.0f / DD) - mu * mu;
        s_mu = mu;
        s_rstd = rsqrtf(var + LNEPS);
    }
    __syncthreads();
    float mu = s_mu, rs = s_rstd;
    float4 g4 = ((const float4*)lng)[threadIdx.x];
    float4 b4 = ((const float4*)lnb)[threadIdx.x];
    float4 o;
    o.x = ((v.x - mu) * rs * g4.x + b4.x) * SCALE;
    o.y = ((v.y - mu) * rs * g4.y + b4.y) * SCALE;
    o.z = ((v.z - mu) * rs * g4.z + b4.z) * SCALE;
    o.w = ((v.w - mu) * rs * g4.w + b4.w) * SCALE;
    ((float4*)(g_qs + (size_t)row * DD))[threadIdx.x] = o;
}

// ---------------------------------------------------------------------------
// attn[b] = qs[b] @ k[b]^T, masked_fill(mask, 0) on write.
// 128x128 tile, BK=16, 256 threads, 8x8 per thread (split 4+4).
// mask is int32 (bool -> int32 in harness).
__global__ __launch_bounds__(256, 2)
void k_gemm(const float* __restrict__ kmat,
            const int* __restrict__ mask,
            float* __restrict__ attn) {
    int b  = blockIdx.z;
    int bm = blockIdx.y * 128;
    int bn = blockIdx.x * 128;
    const float* A  = g_qs + (size_t)b * SS * DD;
    const float* Bk = kmat + (size_t)b * SS * DD;

    __shared__ __align__(16) float As[16][132];
    __shared__ __align__(16) float Bs[16][132];

    int tid = threadIdx.x;
    int tx = tid & 15, ty = tid >> 4;

    float acc[8][8];
    #pragma unroll
    for (int i = 0; i < 8; i++)
        #pragma unroll
        for (int j = 0; j < 8; j++) acc[i][j] = 0.f;

    int lr0 = tid >> 2;           // 0..63
    int lc0 = (tid & 3) * 4;      // 0,4,8,12

    for (int k0 = 0; k0 < DD; k0 += 16) {
        #pragma unroll
        for (int h = 0; h < 2; h++) {
            int r = lr0 + h * 64;
            float4 a  = *(const float4*)&A [(size_t)(bm + r) * DD + k0 + lc0];
            float4 bv = *(const float4*)&Bk[(size_t)(bn + r) * DD + k0 + lc0];
            As[lc0 + 0][r] = a.x;  As[lc0 + 1][r] = a.y;
            As[lc0 + 2][r] = a.z;  As[lc0 + 3][r] = a.w;
            Bs[lc0 + 0][r] = bv.x; Bs[lc0 + 1][r] = bv.y;
            Bs[lc0 + 2][r] = bv.z; Bs[lc0 + 3][r] = bv.w;
        }
        __syncthreads();

        #pragma unroll
        for (int kk = 0; kk < 16; kk++) {
            float ar[8], br[8];
            *(float4*)&ar[0] = *(const float4*)&As[kk][ty * 4];
            *(float4*)&ar[4] = *(const float4*)&As[kk][64 + ty * 4];
            *(float4*)&br[0] = *(const float4*)&Bs[kk][tx * 4];
            *(float4*)&br[4] = *(const float4*)&Bs[kk][64 + tx * 4];
            #pragma unroll
            for (int i = 0; i < 8; i++)
                #pragma unroll
                for (int j = 0; j < 8; j++)
                    acc[i][j] = fmaf(ar[i], br[j], acc[i][j]);
        }
        __syncthreads();
    }

    size_t ab = (size_t)b * SS * SS;
    #pragma unroll
    for (int hm = 0; hm < 2; hm++) {
        #pragma unroll
        for (int i = 0; i < 4; i++) {
            int sRow = bm + hm * 64 + ty * 4 + i;
            size_t rowoff = ab + (size_t)sRow * SS;
            const int* mrow = mask + rowoff;
            #pragma unroll
            for (int hn = 0; hn < 2; hn++) {
                int t0 = bn + hn * 64 + tx * 4;
                int4 m4 = *(const int4*)&mrow[t0];
                float4 o;
                o.x = m4.x ? 0.f : acc[hm * 4 + i][hn * 4 + 0];
                o.y = m4.y ? 0.f : acc[hm * 4 + i][hn * 4 + 1];
                o.z = m4.z ? 0.f : acc[hm * 4 + i][hn * 4 + 2];
                o.w = m4.w ? 0.f : acc[hm * 4 + i][hn * 4 + 3];
                *(float4*)&attn[rowoff + t0] = o;
            }
        }
    }
}

// ---------------------------------------------------------------------------
// rowsum(attn row) then output = rowsum*w + fc_b + q. One block per (b,s).
__global__ void k_out(const float* __restrict__ attn,
                      const float* __restrict__ q,
                      const float* __restrict__ fc_b,
                      float* __restrict__ out) {
    int rid = blockIdx.x;  // 0..B*S-1
    const float4* row = (const float4*)(attn + (size_t)rid * SS);
    float s = 0.f;
    #pragma unroll
    for (int i = 0; i < 2; i++) {
        float4 v = row[threadIdx.x + i * 256];
        s += v.x + v.y + v.z + v.w;
    }
    __shared__ float sh[8];
    __shared__ float s_total;
    #pragma unroll
    for (int off = 16; off > 0; off >>= 1)
        s += __shfl_down_sync(0xffffffffu, s, off);
    int wid = threadIdx.x >> 5, lid = threadIdx.x & 31;
    if (lid == 0) sh[wid] = s;
    __syncthreads();
    if (threadIdx.x == 0) {
        float t = 0.f;
        #pragma unroll
        for (int i = 0; i < 8; i++) t += sh[i];
        s_total = t;
    }
    __syncthreads();
    float rs = s_total;
    float4 w4 = ((const float4*)g_w)[threadIdx.x];
    float4 b4 = ((const float4*)fc_b)[threadIdx.x];
    float4 q4 = ((const float4*)(q + (size_t)rid * DD))[threadIdx.x];
    float4 o;
    o.x = rs * w4.x + b4.x + q4.x;
    o.y = rs * w4.y + b4.y + q4.y;
    o.z = rs * w4.z + b4.z + q4.z;
    o.w = rs * w4.w + b4.w + q4.w;
    ((float4*)(out + (size_t)rid * DD))[threadIdx.x] = o;
}

// ---------------------------------------------------------------------------
extern "C" void kernel_launch(void* const* d_in, const int* in_sizes, int n_in,
                              void* d_out, int out_size) {
    const float* q    = (const float*)d_in[0];
    const float* kmat = (const float*)d_in[1];
    // d_in[2] = v : unused by the reference computation
    const int*   mask = (const int*)d_in[3];
    const float* V    = (const float*)d_in[4];
    const float* fc_w = (const float*)d_in[5];
    const float* fc_b = (const float*)d_in[6];
    const float* ln_g = (const float*)d_in[7];
    const float* ln_b = (const float*)d_in[8];

    float* out  = (float*)d_out;
    float* attn = out + OUT_ELEMS;

    k_w<<<4, 256>>>(fc_w, V);
    k_ln<<<BB * SS, 256>>>(q, ln_g, ln_b);
    dim3 g(SS / 128, SS / 128, BB);
    k_gemm<<<g, 256>>>(kmat, mask, attn);
    k_out<<<BB * SS, 256>>>(attn, q, fc_b, out);
}

// round 6
// speedup vs baseline: 2.5198x; 2.5198x over previous
#include <cuda_runtime.h>
#include <cuda_bf16.h>
#include <stdint.h>

#define BB 4
#define SS 2048
#define DD 1024
#define DVV 64
#define SCALE 0.125f      // 1/sqrt(64)
#define LNEPS 1e-6f
#define OUT_ELEMS (BB*SS*DD)

// GEMM tiling
#define BM 128
#define BN 128
#define BK 64
#define KITERS (DD/BK)            // 16
#define A_HI 0
#define A_LO 16384
#define B_HI 32768
#define B_LO 49152
#define STAGE 65536
#define SMEM_DYN (2*STAGE + 1024)

// scratch (no allocations allowed)
__device__ __nv_bfloat16 g_qhi[BB*SS*DD];
__device__ __nv_bfloat16 g_qlo[BB*SS*DD];
__device__ __nv_bfloat16 g_khi[BB*SS*DD];
__device__ __nv_bfloat16 g_klo[BB*SS*DD];
__device__ float g_w[DD];

// ---------------------------------------------------------------- helpers
__device__ __forceinline__ uint32_t smem_u32(const void* p) {
    uint32_t a;
    asm("{ .reg .u64 t; cvta.to.shared.u64 t, %1; cvt.u32.u64 %0, t; }"
        : "=r"(a) : "l"(p));
    return a;
}
#define SW128(o) ((o) ^ (((o) >> 3) & 0x70))

__device__ __forceinline__ void cpa16(uint32_t dst, const void* src) {
    asm volatile("cp.async.cg.shared.global [%0], [%1], 16;" :: "r"(dst), "l"(src) : "memory");
}
__device__ __forceinline__ void ldsm4(uint32_t* r, uint32_t addr) {
    asm volatile("ldmatrix.sync.aligned.m8n8.x4.shared.b16 {%0,%1,%2,%3}, [%4];"
                 : "=r"(r[0]), "=r"(r[1]), "=r"(r[2]), "=r"(r[3]) : "r"(addr));
}
__device__ __forceinline__ void mma_bf16(float* d, const uint32_t* a, const uint32_t* b) {
    asm volatile(
        "mma.sync.aligned.m16n8k16.row.col.f32.bf16.bf16.f32 "
        "{%0,%1,%2,%3}, {%4,%5,%6,%7}, {%8,%9}, {%0,%1,%2,%3};"
        : "+f"(d[0]), "+f"(d[1]), "+f"(d[2]), "+f"(d[3])
        : "r"(a[0]), "r"(a[1]), "r"(a[2]), "r"(a[3]), "r"(b[0]), "r"(b[1]));
}
__device__ __forceinline__ void split2(float x, __nv_bfloat16& h, __nv_bfloat16& l) {
    h = __float2bfloat16(x);
    l = __float2bfloat16(x - __bfloat162float(h));
}

// ---------------------------------------------------------------------------
__global__ void k_w(const float* __restrict__ fc_w, const float* __restrict__ V) {
    int d = blockIdx.x * blockDim.x + threadIdx.x;
    if (d < DD) {
        float s = 0.f;
        #pragma unroll
        for (int i = 0; i < DVV; i++) s += fc_w[d * DVV + i] * V[i];
        g_w[d] = s;
    }
}

// ---------------------------------------------------------------------------
// LayerNorm + scale -> bf16 hi/lo split. One block (256 thr) per row of 1024.
__global__ void k_ln(const float* __restrict__ q,
                     const float* __restrict__ lng,
                     const float* __restrict__ lnb) {
    int row = blockIdx.x;
    const float4* x4 = (const float4*)(q + (size_t)row * DD);
    float4 v = x4[threadIdx.x];
    float sum = v.x + v.y + v.z + v.w;
    float sq  = v.x * v.x + v.y * v.y + v.z * v.z + v.w * v.w;

    __shared__ float ssum[8], ssq[8];
    __shared__ float s_mu, s_rstd;
    #pragma unroll
    for (int off = 16; off > 0; off >>= 1) {
        sum += __shfl_down_sync(0xffffffffu, sum, off);
        sq  += __shfl_down_sync(0xffffffffu, sq,  off);
    }
    int wid = threadIdx.x >> 5, lid = threadIdx.x & 31;
    if (lid == 0) { ssum[wid] = sum; ssq[wid] = sq; }
    __syncthreads();
    if (threadIdx.x == 0) {
        float ts = 0.f, tq = 0.f;
        #pragma unroll
        for (int i = 0; i < 8; i++) { ts += ssum[i]; tq += ssq[i]; }
        float mu  = ts * (1.0f / DD);
        float var = tq * (1.0f / DD) - mu * mu;
        s_mu = mu;
        s_rstd = rsqrtf(var + LNEPS);
    }
    __syncthreads();
    float mu = s_mu, rs = s_rstd;
    float4 g4 = ((const float4*)lng)[threadIdx.x];
    float4 b4 = ((const float4*)lnb)[threadIdx.x];
    float o[4];
    o[0] = ((v.x - mu) * rs * g4.x + b4.x) * SCALE;
    o[1] = ((v.y - mu) * rs * g4.y + b4.y) * SCALE;
    o[2] = ((v.z - mu) * rs * g4.z + b4.z) * SCALE;
    o[3] = ((v.w - mu) * rs * g4.w + b4.w) * SCALE;
    __nv_bfloat16 h[4], l[4];
    #pragma unroll
    for (int i = 0; i < 4; i++) split2(o[i], h[i], l[i]);
    size_t base = (size_t)row * DD + threadIdx.x * 4;
    *(uint2*)&g_qhi[base] = *(uint2*)h;
    *(uint2*)&g_qlo[base] = *(uint2*)l;
}

// ---------------------------------------------------------------------------
__global__ void k_conv(const float* __restrict__ x) {
    size_t i = ((size_t)blockIdx.x * blockDim.x + threadIdx.x) * 4;
    float4 v = *(const float4*)(x + i);
    float o[4] = {v.x, v.y, v.z, v.w};
    __nv_bfloat16 h[4], l[4];
    #pragma unroll
    for (int j = 0; j < 4; j++) split2(o[j], h[j], l[j]);
    *(uint2*)&g_khi[i] = *(uint2*)h;
    *(uint2*)&g_klo[i] = *(uint2*)l;
}

// ---------------------------------------------------------------------------
// Warp-MMA GEMM: attn = qs @ k^T (bf16 hi/lo x3), masked on write.
// CTA 128x128x64, 8 warps 2(M)x4(N), warp tile 64x32.
__global__ __launch_bounds__(256, 1)
void k_gemm(const int* __restrict__ mask, float* __restrict__ attn) {
    extern __shared__ char dsm[];
    uint32_t sbase = (smem_u32(dsm) + 1023u) & ~1023u;

    int tid = threadIdx.x, wid = tid >> 5, lane = tid & 31;
    int b = blockIdx.z, bm = blockIdx.y * BM, bn = blockIdx.x * BN;

    const __nv_bfloat16* Ah = g_qhi + (size_t)b * SS * DD;
    const __nv_bfloat16* Al = g_qlo + (size_t)b * SS * DD;
    const __nv_bfloat16* Bh = g_khi + (size_t)b * SS * DD;
    const __nv_bfloat16* Bl = g_klo + (size_t)b * SS * DD;

    int j = tid & 7;          // 16B chunk in 128B row
    int r0 = tid >> 3;        // 0..31

    #define LOAD_STAGE(SB, K0) do {                                            \
        uint32_t _sb = (SB); int _k0 = (K0);                                   \
        _Pragma("unroll")                                                      \
        for (int it = 0; it < 4; it++) {                                       \
            int r = r0 + it * 32;                                              \
            uint32_t so = SW128((uint32_t)(r * 128 + j * 16));                 \
            size_t ga = (size_t)(bm + r) * DD + _k0 + j * 8;                   \
            size_t gb = (size_t)(bn + r) * DD + _k0 + j * 8;                   \
            cpa16(_sb + A_HI + so, Ah + ga);                                   \
            cpa16(_sb + A_LO + so, Al + ga);                                   \
            cpa16(_sb + B_HI + so, Bh + gb);                                   \
            cpa16(_sb + B_LO + so, Bl + gb);                                   \
        }                                                                      \
        asm volatile("cp.async.commit_group;" ::: "memory");                   \
    } while (0)

    float acc[4][4][4];
    #pragma unroll
    for (int i = 0; i < 4; i++)
        #pragma unroll
        for (int n = 0; n < 4; n++)
            #pragma unroll
            for (int c = 0; c < 4; c++) acc[i][n][c] = 0.f;

    int wm = (wid & 1) * 64;          // warp M offset in tile
    int wn = (wid >> 1) * 32;         // warp N offset in tile

    // per-lane ldmatrix address components
    int a_r = (lane & 7) + ((lane >> 3) & 1) * 8;   // row within 16
    int a_k = (lane >> 4) * 16;                     // byte k offset
    int b_r = (lane & 7) + (lane >> 4) * 8;         // col within 16
    int b_k = ((lane >> 3) & 1) * 16;

    LOAD_STAGE(sbase, 0);
    LOAD_STAGE(sbase + STAGE, BK);

    for (int kt = 0; kt < KITERS; kt++) {
        if (kt == KITERS - 1) asm volatile("cp.async.wait_group 0;" ::: "memory");
        else                  asm volatile("cp.async.wait_group 1;" ::: "memory");
        __syncthreads();
        uint32_t sb = sbase + (kt & 1) * STAGE;

        #pragma unroll
        for (int ks = 0; ks < 4; ks++) {
            int kb = ks * 32;
            uint32_t ah[4][4], al[4][4], bh[2][4], bl[2][4];
            #pragma unroll
            for (int mt = 0; mt < 4; mt++) {
                uint32_t off = SW128((uint32_t)((wm + mt * 16 + a_r) * 128 + kb + a_k));
                ldsm4(ah[mt], sb + A_HI + off);
                ldsm4(al[mt], sb + A_LO + off);
            }
            #pragma unroll
            for (int bt = 0; bt < 2; bt++) {
                uint32_t off = SW128((uint32_t)((wn + bt * 16 + b_r) * 128 + kb + b_k));
                ldsm4(bh[bt], sb + B_HI + off);
                ldsm4(bl[bt], sb + B_LO + off);
            }
            #pragma unroll
            for (int mt = 0; mt < 4; mt++) {
                #pragma unroll
                for (int nt = 0; nt < 4; nt++) {
                    const uint32_t* bph = &bh[nt >> 1][(nt & 1) * 2];
                    const uint32_t* bpl = &bl[nt >> 1][(nt & 1) * 2];
                    mma_bf16(acc[mt][nt], ah[mt], bph);
                    mma_bf16(acc[mt][nt], ah[mt], bpl);
                    mma_bf16(acc[mt][nt], al[mt], bph);
                }
            }
        }
        __syncthreads();
        if (kt + 2 < KITERS) LOAD_STAGE(sbase + (kt & 1) * STAGE, (kt + 2) * BK);
    }

    // epilogue: masked write of attn
    size_t abase = (size_t)b * SS * SS;
    int qr = lane >> 2, qc = (lane & 3) * 2;
    #pragma unroll
    for (int mt = 0; mt < 4; mt++) {
        int row1 = bm + wm + mt * 16 + qr;
        size_t ro1 = abase + (size_t)row1 * SS;
        size_t ro2 = ro1 + 8 * SS;
        #pragma unroll
        for (int nt = 0; nt < 4; nt++) {
            int col = bn + wn + nt * 8 + qc;
            int2 m1 = *(const int2*)&mask[ro1 + col];
            int2 m2 = *(const int2*)&mask[ro2 + col];
            float2 o1, o2;
            o1.x = m1.x ? 0.f : acc[mt][nt][0];
            o1.y = m1.y ? 0.f : acc[mt][nt][1];
            o2.x = m2.x ? 0.f : acc[mt][nt][2];
            o2.y = m2.y ? 0.f : acc[mt][nt][3];
            *(float2*)&attn[ro1 + col] = o1;
            *(float2*)&attn[ro2 + col] = o2;
        }
    }
}

// ---------------------------------------------------------------------------
// rowsum(attn row) then output = rowsum*w + fc_b + q. One block per (b,s).
__global__ void k_out(const float* __restrict__ attn,
                      const float* __restrict__ q,
                      const float* __restrict__ fc_b,
                      float* __restrict__ out) {
    int rid = blockIdx.x;
    const float4* row = (const float4*)(attn + (size_t)rid * SS);
    float s = 0.f;
    #pragma unroll
    for (int i = 0; i < 2; i++) {
        float4 v = row[threadIdx.x + i * 256];
        s += v.x + v.y + v.z + v.w;
    }
    __shared__ float sh[8];
    __shared__ float s_total;
    #pragma unroll
    for (int off = 16; off > 0; off >>= 1)
        s += __shfl_down_sync(0xffffffffu, s, off);
    int wid = threadIdx.x >> 5, lid = threadIdx.x & 31;
    if (lid == 0) sh[wid] = s;
    __syncthreads();
    if (threadIdx.x == 0) {
        float t = 0.f;
        #pragma unroll
        for (int i = 0; i < 8; i++) t += sh[i];
        s_total = t;
    }
    __syncthreads();
    float rs = s_total;
    float4 w4 = ((const float4*)g_w)[threadIdx.x];
    float4 b4 = ((const float4*)fc_b)[threadIdx.x];
    float4 q4 = ((const float4*)(q + (size_t)rid * DD))[threadIdx.x];
    float4 o;
    o.x = rs * w4.x + b4.x + q4.x;
    o.y = rs * w4.y + b4.y + q4.y;
    o.z = rs * w4.z + b4.z + q4.z;
    o.w = rs * w4.w + b4.w + q4.w;
    ((float4*)(out + (size_t)rid * DD))[threadIdx.x] = o;
}

// ---------------------------------------------------------------------------
extern "C" void kernel_launch(void* const* d_in, const int* in_sizes, int n_in,
                              void* d_out, int out_size) {
    const float* q    = (const float*)d_in[0];
    const float* kmat = (const float*)d_in[1];
    const int*   mask = (const int*)d_in[3];
    const float* V    = (const float*)d_in[4];
    const float* fc_w = (const float*)d_in[5];
    const float* fc_b = (const float*)d_in[6];
    const float* ln_g = (const float*)d_in[7];
    const float* ln_b = (const float*)d_in[8];

    float* out  = (float*)d_out;
    float* attn = out + OUT_ELEMS;

    cudaFuncSetAttribute(k_gemm, cudaFuncAttributeMaxDynamicSharedMemorySize, SMEM_DYN);

    k_w<<<4, 256>>>(fc_w, V);
    k_ln<<<BB * SS, 256>>>(q, ln_g, ln_b);
    k_conv<<<(BB * SS * DD / 4) / 256, 256>>>(kmat);
    dim3 g(SS / BN, SS / BM, BB);
    k_gemm<<<g, 256, SMEM_DYN>>>(mask, attn);
    k_out<<<BB * SS, 256>>>(attn, q, fc_b, out);
}